// round 4
// baseline (speedup 1.0000x reference)
#include <cuda_runtime.h>
#include <cuda_bf16.h>
#include <math.h>
#include <stdint.h>

// ---------------- Problem constants ----------------
#define NN    30000
#define EE    480000
#define ETOT  (EE + NN)
#define FIN   4096
#define D1    512
#define H1    4
#define C1    128
#define CLS   6
#define SLOPE 0.2f

// ---------------- Device scratch ----------------
__device__ float g_h1[(size_t)NN * D1];
__device__ float g_out1[(size_t)NN * D1];
__device__ float g_asrc1[NN * H1];
__device__ float g_adst1[NN * H1];
__device__ float g_h2[NN * CLS];
__device__ float g_as2[NN];
__device__ float g_ad2[NN];
__device__ int   g_deg[NN];
__device__ int   g_off[NN + 1];
__device__ int   g_cur[NN];
__device__ int   g_srcs[ETOT];

// bf16 split operands
__device__ __nv_bfloat16 g_xhi[(size_t)NN * FIN];
__device__ __nv_bfloat16 g_xlo[(size_t)NN * FIN];
__device__ __nv_bfloat16 g_w1thi[(size_t)D1 * FIN];   // transposed: [N=512][K=4096]
__device__ __nv_bfloat16 g_w1tlo[(size_t)D1 * FIN];

__device__ __forceinline__ float lrelu(float v) { return v > 0.0f ? v : SLOPE * v; }

// ==================== helpers ====================
__device__ __forceinline__ uint32_t smem_u32(const void* p) {
    uint32_t a;
    asm("{ .reg .u64 t; cvta.to.shared.u64 t, %1; cvt.u32.u64 %0, t; }" : "=r"(a) : "l"(p));
    return a;
}

__device__ __forceinline__ void cpa16(uint32_t dst, const void* src, uint32_t bytes) {
    asm volatile("cp.async.cg.shared.global [%0], [%1], 16, %2;\n"
                 :: "r"(dst), "l"(src), "r"(bytes) : "memory");
}

__device__ __forceinline__ void ldm_x4(uint32_t addr, uint32_t& r0, uint32_t& r1,
                                       uint32_t& r2, uint32_t& r3) {
    asm volatile("ldmatrix.sync.aligned.m8n8.x4.shared.b16 {%0,%1,%2,%3}, [%4];"
                 : "=r"(r0), "=r"(r1), "=r"(r2), "=r"(r3) : "r"(addr));
}

__device__ __forceinline__ void mma_bf16(float& d0, float& d1, float& d2, float& d3,
                                         uint32_t a0, uint32_t a1, uint32_t a2, uint32_t a3,
                                         uint32_t b0, uint32_t b1) {
    asm volatile("mma.sync.aligned.m16n8k16.row.col.f32.bf16.bf16.f32 "
                 "{%0,%1,%2,%3}, {%4,%5,%6,%7}, {%8,%9}, {%0,%1,%2,%3};"
                 : "+f"(d0), "+f"(d1), "+f"(d2), "+f"(d3)
                 : "r"(a0), "r"(a1), "r"(a2), "r"(a3), "r"(b0), "r"(b1));
}

// ==================== bf16-split conversion ====================
__global__ __launch_bounds__(256) void convx_kernel(const float* __restrict__ x) {
    size_t i = ((size_t)blockIdx.x * 256 + threadIdx.x) * 4;
    if (i >= (size_t)NN * FIN) return;
    float4 v = *(const float4*)(x + i);
    __nv_bfloat16 h0 = __float2bfloat16(v.x);
    __nv_bfloat16 h1 = __float2bfloat16(v.y);
    __nv_bfloat16 h2 = __float2bfloat16(v.z);
    __nv_bfloat16 h3 = __float2bfloat16(v.w);
    __nv_bfloat16 l0 = __float2bfloat16(v.x - __bfloat162float(h0));
    __nv_bfloat16 l1 = __float2bfloat16(v.y - __bfloat162float(h1));
    __nv_bfloat16 l2 = __float2bfloat16(v.z - __bfloat162float(h2));
    __nv_bfloat16 l3 = __float2bfloat16(v.w - __bfloat162float(h3));
    __nv_bfloat162 hv0 = __halves2bfloat162(h0, h1);
    __nv_bfloat162 hv1 = __halves2bfloat162(h2, h3);
    __nv_bfloat162 lv0 = __halves2bfloat162(l0, l1);
    __nv_bfloat162 lv1 = __halves2bfloat162(l2, l3);
    uint2 hv, lv;
    hv.x = *(uint32_t*)&hv0; hv.y = *(uint32_t*)&hv1;
    lv.x = *(uint32_t*)&lv0; lv.y = *(uint32_t*)&lv1;
    *(uint2*)(g_xhi + i) = hv;
    *(uint2*)(g_xlo + i) = lv;
}

// 32x32 smem tile transpose: W1[4096][512] -> W1T hi/lo [512][4096]
__global__ __launch_bounds__(256) void convw1_kernel(const float* __restrict__ W1) {
    __shared__ float tile[32][33];
    const int kb = blockIdx.y * 32;
    const int nb = blockIdx.x * 32;
    const int t = threadIdx.x;
    const int r = t >> 5, c = t & 31;
#pragma unroll
    for (int rr = r; rr < 32; rr += 8)
        tile[rr][c] = W1[(size_t)(kb + rr) * D1 + nb + c];
    __syncthreads();
#pragma unroll
    for (int rr = r; rr < 32; rr += 8) {
        float v = tile[c][rr];   // = W1[kb+c][nb+rr]
        __nv_bfloat16 h = __float2bfloat16(v);
        __nv_bfloat16 l = __float2bfloat16(v - __bfloat162float(h));
        size_t o = (size_t)(nb + rr) * FIN + kb + c;
        g_w1thi[o] = h;
        g_w1tlo[o] = l;
    }
}

// ==================== GEMM1: mma.sync bf16-split, 128x256 CTA tile ====================
#define BK       32
#define CHUNKS   (FIN / BK)         // 128
#define TILE_A_B (128 * 80)         // 10240 bytes (row stride 80B)
#define TILE_B_B (256 * 80)         // 20480 bytes
#define OFF_AHI  0
#define OFF_ALO  (TILE_A_B)
#define OFF_BHI  (2 * TILE_A_B)
#define OFF_BLO  (2 * TILE_A_B + TILE_B_B)
#define STAGE_B  (2 * TILE_A_B + 2 * TILE_B_B)   // 61440
#define NSTAGE   3
#define SMEM_SZ  (NSTAGE * STAGE_B)              // 184320

__global__ __launch_bounds__(256) void mma1_kernel() {
    extern __shared__ __align__(16) char dsm[];
    const uint32_t sb = smem_u32(dsm);

    const int tid = threadIdx.x;
    const int wid = tid >> 5;
    const int lane = tid & 31;
    const int warp_m = wid >> 2;    // 0..1 -> 64 rows each
    const int warp_n = wid & 3;     // 0..3 -> 64 cols each
    const int block_row = blockIdx.y * 128;
    const int nbase = blockIdx.x * 256;

    auto ld_chunk = [&](int c, int s) {
        const uint32_t stg = sb + s * STAGE_B;
        const int kbase = c * BK;
#pragma unroll
        for (int i = tid; i < 512; i += 256) {
            int r = i >> 2, q = i & 3;
            uint32_t dso = (uint32_t)(r * 80 + q * 16);
            int grow = block_row + r;
            uint32_t ok = (grow < NN) ? 16u : 0u;
            size_t se = (size_t)grow * FIN + kbase + q * 8;
            cpa16(stg + OFF_AHI + dso, g_xhi + se, ok);
            cpa16(stg + OFF_ALO + dso, g_xlo + se, ok);
        }
#pragma unroll
        for (int i = tid; i < 1024; i += 256) {
            int r = i >> 2, q = i & 3;
            uint32_t dso = (uint32_t)(r * 80 + q * 16);
            size_t se = (size_t)(nbase + r) * FIN + kbase + q * 8;
            cpa16(stg + OFF_BHI + dso, g_w1thi + se, 16u);
            cpa16(stg + OFF_BLO + dso, g_w1tlo + se, 16u);
        }
    };

    // ldmatrix per-thread base offsets (within a tile)
    const uint32_t a_off = (uint32_t)((warp_m * 64 + (lane & 15)) * 80 + (lane >> 4) * 16);
    const uint32_t b_off = (uint32_t)((warp_n * 64 + (lane & 7) + ((lane >> 4) << 3)) * 80 +
                                      ((lane >> 3) & 1) * 16);

    float acc[4][8][4];
#pragma unroll
    for (int i = 0; i < 4; i++)
#pragma unroll
        for (int j = 0; j < 8; j++)
#pragma unroll
            for (int q = 0; q < 4; q++) acc[i][j][q] = 0.0f;

    // prologue
    ld_chunk(0, 0);
    asm volatile("cp.async.commit_group;\n" ::: "memory");
    ld_chunk(1, 1);
    asm volatile("cp.async.commit_group;\n" ::: "memory");

    for (int c = 0; c < CHUNKS; c++) {
        const int s = c % NSTAGE;
        asm volatile("cp.async.wait_group 1;\n" ::: "memory");
        __syncthreads();

        // issue next loads first (stage (c+2)%3 is free: its readers finished at iter c-1)
        if (c + 2 < CHUNKS) ld_chunk(c + 2, (c + 2) % NSTAGE);
        asm volatile("cp.async.commit_group;\n" ::: "memory");

        const uint32_t stg = sb + s * STAGE_B;
        const uint32_t a_hi = stg + OFF_AHI + a_off;
        const uint32_t a_lo = stg + OFF_ALO + a_off;
        const uint32_t b_hi = stg + OFF_BHI + b_off;
        const uint32_t b_lo = stg + OFF_BLO + b_off;

#pragma unroll
        for (int kk = 0; kk < 2; kk++) {
            uint32_t ahi[4][4], alo[4][4];
#pragma unroll
            for (int i = 0; i < 4; i++) {
                uint32_t ao = (uint32_t)(i * 16 * 80 + kk * 32);
                ldm_x4(a_hi + ao, ahi[i][0], ahi[i][1], ahi[i][2], ahi[i][3]);
                ldm_x4(a_lo + ao, alo[i][0], alo[i][1], alo[i][2], alo[i][3]);
            }
#pragma unroll
            for (int j2 = 0; j2 < 4; j2++) {
                uint32_t bh0, bh1, bh2, bh3, bl0, bl1, bl2, bl3;
                uint32_t bo = (uint32_t)(j2 * 16 * 80 + kk * 32);
                ldm_x4(b_hi + bo, bh0, bh1, bh2, bh3);
                ldm_x4(b_lo + bo, bl0, bl1, bl2, bl3);
#pragma unroll
                for (int i = 0; i < 4; i++) {
                    float* d0 = acc[i][2 * j2];
                    float* d1 = acc[i][2 * j2 + 1];
                    mma_bf16(d0[0], d0[1], d0[2], d0[3],
                             ahi[i][0], ahi[i][1], ahi[i][2], ahi[i][3], bh0, bh1);
                    mma_bf16(d1[0], d1[1], d1[2], d1[3],
                             ahi[i][0], ahi[i][1], ahi[i][2], ahi[i][3], bh2, bh3);
                    mma_bf16(d0[0], d0[1], d0[2], d0[3],
                             ahi[i][0], ahi[i][1], ahi[i][2], ahi[i][3], bl0, bl1);
                    mma_bf16(d1[0], d1[1], d1[2], d1[3],
                             ahi[i][0], ahi[i][1], ahi[i][2], ahi[i][3], bl2, bl3);
                    mma_bf16(d0[0], d0[1], d0[2], d0[3],
                             alo[i][0], alo[i][1], alo[i][2], alo[i][3], bh0, bh1);
                    mma_bf16(d1[0], d1[1], d1[2], d1[3],
                             alo[i][0], alo[i][1], alo[i][2], alo[i][3], bh2, bh3);
                }
            }
        }
    }

    // epilogue
#pragma unroll
    for (int i = 0; i < 4; i++) {
        int row0 = block_row + warp_m * 64 + i * 16 + (lane >> 2);
#pragma unroll
        for (int j = 0; j < 8; j++) {
            int col = nbase + warp_n * 64 + j * 8 + (lane & 3) * 2;
            if (row0 < NN)
                *(float2*)(g_h1 + (size_t)row0 * D1 + col) = make_float2(acc[i][j][0], acc[i][j][1]);
            if (row0 + 8 < NN)
                *(float2*)(g_h1 + (size_t)(row0 + 8) * D1 + col) = make_float2(acc[i][j][2], acc[i][j][3]);
        }
    }
}

// ==================== CSR build ====================
__global__ void zero_deg_kernel() {
    int i = blockIdx.x * blockDim.x + threadIdx.x;
    if (i < NN) g_deg[i] = 0;
}

__global__ void count_kernel(const int* __restrict__ ei) {
    int e = blockIdx.x * blockDim.x + threadIdx.x;
    if (e >= ETOT) return;
    int dst = (e < EE) ? ei[EE + e] : (e - EE);
    atomicAdd(&g_deg[dst], 1);
}

__global__ __launch_bounds__(1024) void scan_kernel() {
    __shared__ int part[1024];
    const int t = threadIdx.x;
    const int CH = (NN + 1023) / 1024;
    const int base = t * CH;
    int s = 0;
    for (int i = 0; i < CH; i++) {
        int idx = base + i;
        if (idx < NN) s += g_deg[idx];
    }
    part[t] = s;
    __syncthreads();
    for (int o = 1; o < 1024; o <<= 1) {
        int v = (t >= o) ? part[t - o] : 0;
        __syncthreads();
        part[t] += v;
        __syncthreads();
    }
    int run = part[t] - s;
    for (int i = 0; i < CH; i++) {
        int idx = base + i;
        if (idx < NN) {
            g_off[idx] = run;
            g_cur[idx] = run;
            run += g_deg[idx];
        }
    }
    if (t == 1023) g_off[NN] = part[1023];
}

__global__ void scatter_kernel(const int* __restrict__ ei) {
    int e = blockIdx.x * blockDim.x + threadIdx.x;
    if (e >= ETOT) return;
    int src, dst;
    if (e < EE) { src = ei[e]; dst = ei[EE + e]; }
    else        { src = e - EE; dst = e - EE; }
    int pos = atomicAdd(&g_cur[dst], 1);
    g_srcs[pos] = src;
}

// ==================== Layer 1 alphas ====================
__global__ void alpha1_kernel(const float* __restrict__ a_s, const float* __restrict__ a_d) {
    int warp = blockIdx.x * 8 + (threadIdx.x >> 5);
    int lane = threadIdx.x & 31;
    if (warp >= NN) return;
    const float* row = g_h1 + (size_t)warp * D1;
#pragma unroll
    for (int h = 0; h < H1; h++) {
        float ss = 0.f, sd = 0.f;
#pragma unroll
        for (int k = 0; k < 4; k++) {
            int c = h * C1 + lane + 32 * k;
            float v = row[c];
            ss = fmaf(v, a_s[c], ss);
            sd = fmaf(v, a_d[c], sd);
        }
#pragma unroll
        for (int o = 16; o; o >>= 1) {
            ss += __shfl_xor_sync(0xffffffffu, ss, o);
            sd += __shfl_xor_sync(0xffffffffu, sd, o);
        }
        if (lane == 0) {
            g_asrc1[warp * H1 + h] = ss;
            g_adst1[warp * H1 + h] = sd;
        }
    }
}

// ==================== Layer 1 softmax + aggregate + ELU ====================
__global__ __launch_bounds__(128) void agg1_kernel(const float* __restrict__ b1) {
    const int n = blockIdx.x;
    const int t = threadIdx.x;
    const int s0 = g_off[n];
    const int deg = g_off[n + 1] - s0;

    __shared__ float adsts[H1];
    __shared__ float sm[H1];
    __shared__ float sinv[H1];
    __shared__ float red[128 * H1];
    __shared__ int   ssrc[128];
    __shared__ float scoef[128 * H1];

    if (t < H1) adsts[t] = g_adst1[n * H1 + t];
    __syncthreads();

    float lm[H1] = {-INFINITY, -INFINITY, -INFINITY, -INFINITY};
    for (int i = t; i < deg; i += 128) {
        int s = g_srcs[s0 + i];
#pragma unroll
        for (int h = 0; h < H1; h++) {
            float l = lrelu(g_asrc1[s * H1 + h] + adsts[h]);
            lm[h] = fmaxf(lm[h], l);
        }
    }
#pragma unroll
    for (int h = 0; h < H1; h++) red[t * H1 + h] = lm[h];
    __syncthreads();
    if (t < H1) {
        float m = -INFINITY;
        for (int i = 0; i < 128; i++) m = fmaxf(m, red[i * H1 + t]);
        sm[t] = m;
    }
    __syncthreads();

    float ls[H1] = {0.f, 0.f, 0.f, 0.f};
    for (int i = t; i < deg; i += 128) {
        int s = g_srcs[s0 + i];
#pragma unroll
        for (int h = 0; h < H1; h++) {
            float l = lrelu(g_asrc1[s * H1 + h] + adsts[h]);
            ls[h] += expf(l - sm[h]);
        }
    }
#pragma unroll
    for (int h = 0; h < H1; h++) red[t * H1 + h] = ls[h];
    __syncthreads();
    if (t < H1) {
        float s = 0.f;
        for (int i = 0; i < 128; i++) s += red[i * H1 + t];
        sinv[t] = 1.0f / s;
    }
    __syncthreads();

    float acc0 = 0.f, acc1 = 0.f, acc2 = 0.f, acc3 = 0.f;
    for (int base = 0; base < deg; base += 128) {
        int cnt = min(128, deg - base);
        if (t < cnt) {
            int s = g_srcs[s0 + base + t];
            ssrc[t] = s;
#pragma unroll
            for (int h = 0; h < H1; h++) {
                float l = lrelu(g_asrc1[s * H1 + h] + adsts[h]);
                scoef[t * H1 + h] = expf(l - sm[h]) * sinv[h];
            }
        }
        __syncthreads();
        for (int i = 0; i < cnt; i++) {
            const float* hp = g_h1 + (size_t)ssrc[i] * D1 + t;
            float c0 = scoef[i * H1 + 0];
            float c1 = scoef[i * H1 + 1];
            float c2 = scoef[i * H1 + 2];
            float c3 = scoef[i * H1 + 3];
            acc0 = fmaf(c0, hp[0],      acc0);
            acc1 = fmaf(c1, hp[C1],     acc1);
            acc2 = fmaf(c2, hp[2 * C1], acc2);
            acc3 = fmaf(c3, hp[3 * C1], acc3);
        }
        __syncthreads();
    }

    float* orow = g_out1 + (size_t)n * D1;
    float v;
    v = acc0 + b1[t];           orow[t]          = v > 0.f ? v : expm1f(v);
    v = acc1 + b1[C1 + t];      orow[C1 + t]     = v > 0.f ? v : expm1f(v);
    v = acc2 + b1[2 * C1 + t];  orow[2 * C1 + t] = v > 0.f ? v : expm1f(v);
    v = acc3 + b1[3 * C1 + t];  orow[3 * C1 + t] = v > 0.f ? v : expm1f(v);
}

// ==================== Layer 2 ====================
__global__ __launch_bounds__(256) void gemm2_kernel(const float* __restrict__ W2) {
    __shared__ float w[D1 * CLS];
    int t = threadIdx.x;
    for (int i = t; i < D1 * CLS; i += 256) w[i] = W2[i];
    __syncthreads();
    int warp = blockIdx.x * 8 + (t >> 5);
    int lane = t & 31;
    if (warp >= NN) return;
    const float* row = g_out1 + (size_t)warp * D1;
    float acc[CLS] = {0.f, 0.f, 0.f, 0.f, 0.f, 0.f};
    for (int k = lane; k < D1; k += 32) {
        float v = row[k];
        const float* wr = &w[k * CLS];
#pragma unroll
        for (int c = 0; c < CLS; c++) acc[c] = fmaf(v, wr[c], acc[c]);
    }
#pragma unroll
    for (int o = 16; o; o >>= 1)
#pragma unroll
        for (int c = 0; c < CLS; c++) acc[c] += __shfl_xor_sync(0xffffffffu, acc[c], o);
    if (lane == 0) {
#pragma unroll
        for (int c = 0; c < CLS; c++) g_h2[warp * CLS + c] = acc[c];
    }
}

__global__ void alpha2_kernel(const float* __restrict__ a_s, const float* __restrict__ a_d) {
    int n = blockIdx.x * blockDim.x + threadIdx.x;
    if (n >= NN) return;
    float s = 0.f, d = 0.f;
#pragma unroll
    for (int c = 0; c < CLS; c++) {
        float v = g_h2[n * CLS + c];
        s = fmaf(v, a_s[c], s);
        d = fmaf(v, a_d[c], d);
    }
    g_as2[n] = s;
    g_ad2[n] = d;
}

__global__ __launch_bounds__(128) void agg2_kernel(const float* __restrict__ b2,
                                                   float* __restrict__ out) {
    int n = blockIdx.x * 4 + (threadIdx.x >> 5);
    int lane = threadIdx.x & 31;
    if (n >= NN) return;
    int s0 = g_off[n];
    int deg = g_off[n + 1] - s0;
    float ad = g_ad2[n];

    float lmax = -INFINITY;
    for (int i = lane; i < deg; i += 32) {
        int s = g_srcs[s0 + i];
        lmax = fmaxf(lmax, lrelu(g_as2[s] + ad));
    }
#pragma unroll
    for (int o = 16; o; o >>= 1) lmax = fmaxf(lmax, __shfl_xor_sync(0xffffffffu, lmax, o));

    float lsum = 0.f;
    for (int i = lane; i < deg; i += 32) {
        int s = g_srcs[s0 + i];
        lsum += expf(lrelu(g_as2[s] + ad) - lmax);
    }
#pragma unroll
    for (int o = 16; o; o >>= 1) lsum += __shfl_xor_sync(0xffffffffu, lsum, o);
    float inv = 1.0f / lsum;

    float acc[CLS] = {0.f, 0.f, 0.f, 0.f, 0.f, 0.f};
    for (int i = lane; i < deg; i += 32) {
        int s = g_srcs[s0 + i];
        float coef = expf(lrelu(g_as2[s] + ad) - lmax) * inv;
        const float* hp = g_h2 + s * CLS;
#pragma unroll
        for (int c = 0; c < CLS; c++) acc[c] = fmaf(coef, hp[c], acc[c]);
    }
#pragma unroll
    for (int o = 16; o; o >>= 1)
#pragma unroll
        for (int c = 0; c < CLS; c++) acc[c] += __shfl_xor_sync(0xffffffffu, acc[c], o);

    if (lane == 0) {
#pragma unroll
        for (int c = 0; c < CLS; c++) out[n * CLS + c] = acc[c] + b2[c];
    }
}

// ==================== Launch ====================
extern "C" void kernel_launch(void* const* d_in, const int* in_sizes, int n_in,
                              void* d_out, int out_size) {
    const float* x   = (const float*)d_in[0];
    const int*   ei  = (const int*)  d_in[1];
    const float* W1  = (const float*)d_in[2];
    const float* as1 = (const float*)d_in[3];
    const float* ad1 = (const float*)d_in[4];
    const float* b1  = (const float*)d_in[5];
    const float* W2  = (const float*)d_in[6];
    const float* as2 = (const float*)d_in[7];
    const float* ad2 = (const float*)d_in[8];
    const float* b2  = (const float*)d_in[9];
    float* out = (float*)d_out;

    static bool attr_set = false;
    if (!attr_set) {
        cudaFuncSetAttribute(mma1_kernel, cudaFuncAttributeMaxDynamicSharedMemorySize, SMEM_SZ);
        attr_set = true;
    }

    // CSR build
    zero_deg_kernel<<<(NN + 255) / 256, 256>>>();
    count_kernel<<<(ETOT + 255) / 256, 256>>>(ei);
    scan_kernel<<<1, 1024>>>();
    scatter_kernel<<<(ETOT + 255) / 256, 256>>>(ei);

    // bf16 split conversion
    convx_kernel<<<(int)(((size_t)NN * FIN / 4 + 255) / 256), 256>>>(x);
    convw1_kernel<<<dim3(D1 / 32, FIN / 32), 256>>>(W1);

    // Layer 1: mma.sync GEMM + attention
    mma1_kernel<<<dim3(D1 / 256, (NN + 127) / 128), 256, SMEM_SZ>>>();
    alpha1_kernel<<<(NN + 7) / 8, 256>>>(as1, ad1);
    agg1_kernel<<<NN, 128>>>(b1);

    // Layer 2
    gemm2_kernel<<<(NN + 7) / 8, 256>>>(W2);
    alpha2_kernel<<<(NN + 255) / 256, 256>>>(as2, ad2);
    agg2_kernel<<<(NN + 3) / 4, 128>>>(b2, out);
}

// round 5
// speedup vs baseline: 1.2462x; 1.2462x over previous
#include <cuda_runtime.h>
#include <cuda_bf16.h>
#include <math.h>
#include <stdint.h>

// ---------------- Problem constants ----------------
#define NN    30000
#define EE    480000
#define ETOT  (EE + NN)
#define FIN   4096
#define D1    512
#define H1    4
#define C1    128
#define CLS   6
#define SLOPE 0.2f

// ---------------- Device scratch ----------------
__device__ float g_h1[(size_t)NN * D1];
__device__ float g_out1[(size_t)NN * D1];
__device__ float g_asrc1[NN * H1];
__device__ float g_adst1[NN * H1];
__device__ float g_h2[NN * CLS];
__device__ float g_as2[NN];
__device__ float g_ad2[NN];
__device__ int   g_deg[NN];
__device__ int   g_off[NN + 1];
__device__ int   g_cur[NN];
__device__ int   g_srcs[ETOT];

// bf16 split W1 (transposed): [N=512][K=4096]
__device__ __nv_bfloat16 g_w1thi[(size_t)D1 * FIN];
__device__ __nv_bfloat16 g_w1tlo[(size_t)D1 * FIN];

__device__ __forceinline__ float lrelu(float v) { return v > 0.0f ? v : SLOPE * v; }

// ==================== helpers ====================
__device__ __forceinline__ uint32_t smem_u32(const void* p) {
    uint32_t a;
    asm("{ .reg .u64 t; cvta.to.shared.u64 t, %1; cvt.u32.u64 %0, t; }" : "=r"(a) : "l"(p));
    return a;
}

__device__ __forceinline__ void cpa16(uint32_t dst, const void* src) {
    asm volatile("cp.async.cg.shared.global [%0], [%1], 16;\n"
                 :: "r"(dst), "l"(src) : "memory");
}

__device__ __forceinline__ void ldm_x4(uint32_t addr, uint32_t& r0, uint32_t& r1,
                                       uint32_t& r2, uint32_t& r3) {
    asm volatile("ldmatrix.sync.aligned.m8n8.x4.shared.b16 {%0,%1,%2,%3}, [%4];"
                 : "=r"(r0), "=r"(r1), "=r"(r2), "=r"(r3) : "r"(addr));
}

__device__ __forceinline__ void mma_bf16(float& d0, float& d1, float& d2, float& d3,
                                         uint32_t a0, uint32_t a1, uint32_t a2, uint32_t a3,
                                         uint32_t b0, uint32_t b1) {
    asm volatile("mma.sync.aligned.m16n8k16.row.col.f32.bf16.bf16.f32 "
                 "{%0,%1,%2,%3}, {%4,%5,%6,%7}, {%8,%9}, {%0,%1,%2,%3};"
                 : "+f"(d0), "+f"(d1), "+f"(d2), "+f"(d3)
                 : "r"(a0), "r"(a1), "r"(a2), "r"(a3), "r"(b0), "r"(b1));
}

__device__ __forceinline__ uint32_t pack_hi(float a, float b) {
    __nv_bfloat162 h = __halves2bfloat162(__float2bfloat16(a), __float2bfloat16(b));
    return *(uint32_t*)&h;
}
__device__ __forceinline__ uint32_t pack_lo(float a, float b) {
    __nv_bfloat16 ha = __float2bfloat16(a);
    __nv_bfloat16 hb = __float2bfloat16(b);
    __nv_bfloat162 l = __halves2bfloat162(__float2bfloat16(a - __bfloat162float(ha)),
                                          __float2bfloat16(b - __bfloat162float(hb)));
    return *(uint32_t*)&l;
}

// ==================== W1 conversion (32x32 tile transpose) ====================
__global__ __launch_bounds__(256) void convw1_kernel(const float* __restrict__ W1) {
    __shared__ float tile[32][33];
    const int kb = blockIdx.y * 32;
    const int nb = blockIdx.x * 32;
    const int t = threadIdx.x;
    const int r = t >> 5, c = t & 31;
#pragma unroll
    for (int rr = r; rr < 32; rr += 8)
        tile[rr][c] = W1[(size_t)(kb + rr) * D1 + nb + c];
    __syncthreads();
#pragma unroll
    for (int rr = r; rr < 32; rr += 8) {
        float v = tile[c][rr];
        __nv_bfloat16 h = __float2bfloat16(v);
        __nv_bfloat16 l = __float2bfloat16(v - __bfloat162float(h));
        size_t o = (size_t)(nb + rr) * FIN + kb + c;
        g_w1thi[o] = h;
        g_w1tlo[o] = l;
    }
}

// ==================== GEMM1: fused-convert bf16-split mma.sync ====================
// 128x128 CTA tile, BK=32, 2-stage, 2 CTAs/SM.
#define BK       32
#define CHUNKS   (FIN / BK)      // 128
#define TILE_T   (128 * 80)      // 10240 B per operand tile
#define OFF_AHI  0
#define OFF_ALO  (TILE_T)
#define OFF_BHI  (2 * TILE_T)
#define OFF_BLO  (3 * TILE_T)
#define STAGE_B  (4 * TILE_T)    // 40960
#define SMEM_SZ  (2 * STAGE_B)   // 81920

__global__ __launch_bounds__(256, 2) void mma1_kernel(const float* __restrict__ x) {
    extern __shared__ __align__(16) char dsm[];
    const uint32_t sb = smem_u32(dsm);

    const int tid = threadIdx.x;
    const int wid = tid >> 5;
    const int lane = tid & 31;
    const int warp_m = wid >> 2;    // 0..1
    const int warp_n = wid & 3;     // 0..3
    const int block_row = blockIdx.y * 128;
    const int nbase = blockIdx.x * 128;

    // A reg-staging: thread owns row r = tid>>1, 16 floats at col half*16
    const int a_r = tid >> 1;
    const int a_half = tid & 1;
    const bool a_ok = (block_row + a_r) < NN;
    const float* a_src = x + (size_t)(block_row + a_r) * FIN + a_half * 16;
    const uint32_t a_dso = (uint32_t)(a_r * 80 + a_half * 32);

    float4 xr[4];
    auto ldA = [&](int c) {
        if (a_ok) {
            const float4* p = (const float4*)(a_src + c * BK);
#pragma unroll
            for (int q = 0; q < 4; q++) xr[q] = p[q];
        } else {
            float4 z = make_float4(0.f, 0.f, 0.f, 0.f);
#pragma unroll
            for (int q = 0; q < 4; q++) xr[q] = z;
        }
    };
    auto stsA = [&](int s) {
        const uint32_t base = sb + s * STAGE_B;
        uint4 h0, h1, l0, l1;
        h0.x = pack_hi(xr[0].x, xr[0].y); h0.y = pack_hi(xr[0].z, xr[0].w);
        h0.z = pack_hi(xr[1].x, xr[1].y); h0.w = pack_hi(xr[1].z, xr[1].w);
        h1.x = pack_hi(xr[2].x, xr[2].y); h1.y = pack_hi(xr[2].z, xr[2].w);
        h1.z = pack_hi(xr[3].x, xr[3].y); h1.w = pack_hi(xr[3].z, xr[3].w);
        l0.x = pack_lo(xr[0].x, xr[0].y); l0.y = pack_lo(xr[0].z, xr[0].w);
        l0.z = pack_lo(xr[1].x, xr[1].y); l0.w = pack_lo(xr[1].z, xr[1].w);
        l1.x = pack_lo(xr[2].x, xr[2].y); l1.y = pack_lo(xr[2].z, xr[2].w);
        l1.z = pack_lo(xr[3].x, xr[3].y); l1.w = pack_lo(xr[3].z, xr[3].w);
        uint32_t ah = base + OFF_AHI + a_dso;
        uint32_t al = base + OFF_ALO + a_dso;
        asm volatile("st.shared.v4.b32 [%0], {%1,%2,%3,%4};" :: "r"(ah), "r"(h0.x), "r"(h0.y), "r"(h0.z), "r"(h0.w));
        asm volatile("st.shared.v4.b32 [%0], {%1,%2,%3,%4};" :: "r"(ah + 16), "r"(h1.x), "r"(h1.y), "r"(h1.z), "r"(h1.w));
        asm volatile("st.shared.v4.b32 [%0], {%1,%2,%3,%4};" :: "r"(al), "r"(l0.x), "r"(l0.y), "r"(l0.z), "r"(l0.w));
        asm volatile("st.shared.v4.b32 [%0], {%1,%2,%3,%4};" :: "r"(al + 16), "r"(l1.x), "r"(l1.y), "r"(l1.z), "r"(l1.w));
    };

    auto cpB = [&](int c, int s) {
        const uint32_t base = sb + s * STAGE_B;
        const int kbase = c * BK;
#pragma unroll
        for (int i = tid; i < 512; i += 256) {
            int r = i >> 2, q = i & 3;
            uint32_t dso = (uint32_t)(r * 80 + q * 16);
            size_t se = (size_t)(nbase + r) * FIN + kbase + q * 8;
            cpa16(base + OFF_BHI + dso, g_w1thi + se);
            cpa16(base + OFF_BLO + dso, g_w1tlo + se);
        }
    };

    const uint32_t a_off = (uint32_t)((warp_m * 64 + (lane & 15)) * 80 + (lane >> 4) * 16);
    const uint32_t b_off = (uint32_t)((warp_n * 32 + (lane & 7) + ((lane >> 4) << 3)) * 80 +
                                      ((lane >> 3) & 1) * 16);

    float acc[4][4][4];
#pragma unroll
    for (int i = 0; i < 4; i++)
#pragma unroll
        for (int j = 0; j < 4; j++)
#pragma unroll
            for (int q = 0; q < 4; q++) acc[i][j][q] = 0.0f;

    // prologue: fill stage 0 with chunk 0; preload chunk 1 into regs
    ldA(0);
    stsA(0);
    cpB(0, 0);
    asm volatile("cp.async.commit_group;\n" ::: "memory");
    ldA(1);

    for (int c = 0; c < CHUNKS; c++) {
        const int s = c & 1;
        asm volatile("cp.async.wait_group 0;\n" ::: "memory");  // B_c complete
        __syncthreads();                                        // stage s^1 readers done; B_c visible

        if (c + 1 < CHUNKS) {
            stsA(s ^ 1);          // A_{c+1}
            cpB(c + 1, s ^ 1);
            asm volatile("cp.async.commit_group;\n" ::: "memory");
        }
        if (c + 2 < CHUNKS) ldA(c + 2);

        const uint32_t stg = sb + s * STAGE_B;
        const uint32_t a_hi = stg + OFF_AHI + a_off;
        const uint32_t a_lo = stg + OFF_ALO + a_off;
        const uint32_t b_hi = stg + OFF_BHI + b_off;
        const uint32_t b_lo = stg + OFF_BLO + b_off;

#pragma unroll
        for (int kk = 0; kk < 2; kk++) {
            uint32_t ahi[4][4], alo[4][4];
#pragma unroll
            for (int i = 0; i < 4; i++) {
                uint32_t ao = (uint32_t)(i * 16 * 80 + kk * 32);
                ldm_x4(a_hi + ao, ahi[i][0], ahi[i][1], ahi[i][2], ahi[i][3]);
                ldm_x4(a_lo + ao, alo[i][0], alo[i][1], alo[i][2], alo[i][3]);
            }
#pragma unroll
            for (int j2 = 0; j2 < 2; j2++) {
                uint32_t bh0, bh1, bh2, bh3, bl0, bl1, bl2, bl3;
                uint32_t bo = (uint32_t)(j2 * 16 * 80 + kk * 32);
                ldm_x4(b_hi + bo, bh0, bh1, bh2, bh3);
                ldm_x4(b_lo + bo, bl0, bl1, bl2, bl3);
#pragma unroll
                for (int i = 0; i < 4; i++) {
                    float* d0 = acc[i][2 * j2];
                    float* d1 = acc[i][2 * j2 + 1];
                    mma_bf16(d0[0], d0[1], d0[2], d0[3],
                             ahi[i][0], ahi[i][1], ahi[i][2], ahi[i][3], bh0, bh1);
                    mma_bf16(d1[0], d1[1], d1[2], d1[3],
                             ahi[i][0], ahi[i][1], ahi[i][2], ahi[i][3], bh2, bh3);
                    mma_bf16(d0[0], d0[1], d0[2], d0[3],
                             ahi[i][0], ahi[i][1], ahi[i][2], ahi[i][3], bl0, bl1);
                    mma_bf16(d1[0], d1[1], d1[2], d1[3],
                             ahi[i][0], ahi[i][1], ahi[i][2], ahi[i][3], bl2, bl3);
                    mma_bf16(d0[0], d0[1], d0[2], d0[3],
                             alo[i][0], alo[i][1], alo[i][2], alo[i][3], bh0, bh1);
                    mma_bf16(d1[0], d1[1], d1[2], d1[3],
                             alo[i][0], alo[i][1], alo[i][2], alo[i][3], bh2, bh3);
                }
            }
        }
    }

    // epilogue
#pragma unroll
    for (int i = 0; i < 4; i++) {
        int row0 = block_row + warp_m * 64 + i * 16 + (lane >> 2);
#pragma unroll
        for (int j = 0; j < 4; j++) {
            int col = nbase + warp_n * 32 + j * 8 + (lane & 3) * 2;
            if (row0 < NN)
                *(float2*)(g_h1 + (size_t)row0 * D1 + col) = make_float2(acc[i][j][0], acc[i][j][1]);
            if (row0 + 8 < NN)
                *(float2*)(g_h1 + (size_t)(row0 + 8) * D1 + col) = make_float2(acc[i][j][2], acc[i][j][3]);
        }
    }
}

// ==================== CSR build ====================
__global__ void zero_deg_kernel() {
    int i = blockIdx.x * blockDim.x + threadIdx.x;
    if (i < NN) g_deg[i] = 0;
}

__global__ void count_kernel(const int* __restrict__ ei) {
    int e = blockIdx.x * blockDim.x + threadIdx.x;
    if (e >= ETOT) return;
    int dst = (e < EE) ? ei[EE + e] : (e - EE);
    atomicAdd(&g_deg[dst], 1);
}

__global__ __launch_bounds__(1024) void scan_kernel() {
    __shared__ int part[1024];
    const int t = threadIdx.x;
    const int CH = (NN + 1023) / 1024;
    const int base = t * CH;
    int s = 0;
    for (int i = 0; i < CH; i++) {
        int idx = base + i;
        if (idx < NN) s += g_deg[idx];
    }
    part[t] = s;
    __syncthreads();
    for (int o = 1; o < 1024; o <<= 1) {
        int v = (t >= o) ? part[t - o] : 0;
        __syncthreads();
        part[t] += v;
        __syncthreads();
    }
    int run = part[t] - s;
    for (int i = 0; i < CH; i++) {
        int idx = base + i;
        if (idx < NN) {
            g_off[idx] = run;
            g_cur[idx] = run;
            run += g_deg[idx];
        }
    }
    if (t == 1023) g_off[NN] = part[1023];
}

__global__ void scatter_kernel(const int* __restrict__ ei) {
    int e = blockIdx.x * blockDim.x + threadIdx.x;
    if (e >= ETOT) return;
    int src, dst;
    if (e < EE) { src = ei[e]; dst = ei[EE + e]; }
    else        { src = e - EE; dst = e - EE; }
    int pos = atomicAdd(&g_cur[dst], 1);
    g_srcs[pos] = src;
}

// ==================== Layer 1 alphas ====================
__global__ void alpha1_kernel(const float* __restrict__ a_s, const float* __restrict__ a_d) {
    int warp = blockIdx.x * 8 + (threadIdx.x >> 5);
    int lane = threadIdx.x & 31;
    if (warp >= NN) return;
    const float* row = g_h1 + (size_t)warp * D1;
#pragma unroll
    for (int h = 0; h < H1; h++) {
        float ss = 0.f, sd = 0.f;
#pragma unroll
        for (int k = 0; k < 4; k++) {
            int c = h * C1 + lane + 32 * k;
            float v = row[c];
            ss = fmaf(v, a_s[c], ss);
            sd = fmaf(v, a_d[c], sd);
        }
#pragma unroll
        for (int o = 16; o; o >>= 1) {
            ss += __shfl_xor_sync(0xffffffffu, ss, o);
            sd += __shfl_xor_sync(0xffffffffu, sd, o);
        }
        if (lane == 0) {
            g_asrc1[warp * H1 + h] = ss;
            g_adst1[warp * H1 + h] = sd;
        }
    }
}

// ==================== Layer 1 softmax + aggregate + ELU ====================
__global__ __launch_bounds__(128) void agg1_kernel(const float* __restrict__ b1) {
    const int n = blockIdx.x;
    const int t = threadIdx.x;
    const int s0 = g_off[n];
    const int deg = g_off[n + 1] - s0;

    __shared__ float adsts[H1];
    __shared__ float sm[H1];
    __shared__ float sinv[H1];
    __shared__ float red[128 * H1];
    __shared__ int   ssrc[128];
    __shared__ float scoef[128 * H1];

    if (t < H1) adsts[t] = g_adst1[n * H1 + t];
    __syncthreads();

    float lm[H1] = {-INFINITY, -INFINITY, -INFINITY, -INFINITY};
    for (int i = t; i < deg; i += 128) {
        int s = g_srcs[s0 + i];
#pragma unroll
        for (int h = 0; h < H1; h++) {
            float l = lrelu(g_asrc1[s * H1 + h] + adsts[h]);
            lm[h] = fmaxf(lm[h], l);
        }
    }
#pragma unroll
    for (int h = 0; h < H1; h++) red[t * H1 + h] = lm[h];
    __syncthreads();
    if (t < H1) {
        float m = -INFINITY;
        for (int i = 0; i < 128; i++) m = fmaxf(m, red[i * H1 + t]);
        sm[t] = m;
    }
    __syncthreads();

    float ls[H1] = {0.f, 0.f, 0.f, 0.f};
    for (int i = t; i < deg; i += 128) {
        int s = g_srcs[s0 + i];
#pragma unroll
        for (int h = 0; h < H1; h++) {
            float l = lrelu(g_asrc1[s * H1 + h] + adsts[h]);
            ls[h] += expf(l - sm[h]);
        }
    }
#pragma unroll
    for (int h = 0; h < H1; h++) red[t * H1 + h] = ls[h];
    __syncthreads();
    if (t < H1) {
        float s = 0.f;
        for (int i = 0; i < 128; i++) s += red[i * H1 + t];
        sinv[t] = 1.0f / s;
    }
    __syncthreads();

    float acc0 = 0.f, acc1 = 0.f, acc2 = 0.f, acc3 = 0.f;
    for (int base = 0; base < deg; base += 128) {
        int cnt = min(128, deg - base);
        if (t < cnt) {
            int s = g_srcs[s0 + base + t];
            ssrc[t] = s;
#pragma unroll
            for (int h = 0; h < H1; h++) {
                float l = lrelu(g_asrc1[s * H1 + h] + adsts[h]);
                scoef[t * H1 + h] = expf(l - sm[h]) * sinv[h];
            }
        }
        __syncthreads();
        for (int i = 0; i < cnt; i++) {
            const float* hp = g_h1 + (size_t)ssrc[i] * D1 + t;
            float c0 = scoef[i * H1 + 0];
            float c1 = scoef[i * H1 + 1];
            float c2 = scoef[i * H1 + 2];
            float c3 = scoef[i * H1 + 3];
            acc0 = fmaf(c0, hp[0],      acc0);
            acc1 = fmaf(c1, hp[C1],     acc1);
            acc2 = fmaf(c2, hp[2 * C1], acc2);
            acc3 = fmaf(c3, hp[3 * C1], acc3);
        }
        __syncthreads();
    }

    float* orow = g_out1 + (size_t)n * D1;
    float v;
    v = acc0 + b1[t];           orow[t]          = v > 0.f ? v : expm1f(v);
    v = acc1 + b1[C1 + t];      orow[C1 + t]     = v > 0.f ? v : expm1f(v);
    v = acc2 + b1[2 * C1 + t];  orow[2 * C1 + t] = v > 0.f ? v : expm1f(v);
    v = acc3 + b1[3 * C1 + t];  orow[3 * C1 + t] = v > 0.f ? v : expm1f(v);
}

// ==================== Layer 2 ====================
__global__ __launch_bounds__(256) void gemm2_kernel(const float* __restrict__ W2) {
    __shared__ float w[D1 * CLS];
    int t = threadIdx.x;
    for (int i = t; i < D1 * CLS; i += 256) w[i] = W2[i];
    __syncthreads();
    int warp = blockIdx.x * 8 + (t >> 5);
    int lane = t & 31;
    if (warp >= NN) return;
    const float* row = g_out1 + (size_t)warp * D1;
    float acc[CLS] = {0.f, 0.f, 0.f, 0.f, 0.f, 0.f};
    for (int k = lane; k < D1; k += 32) {
        float v = row[k];
        const float* wr = &w[k * CLS];
#pragma unroll
        for (int c = 0; c < CLS; c++) acc[c] = fmaf(v, wr[c], acc[c]);
    }
#pragma unroll
    for (int o = 16; o; o >>= 1)
#pragma unroll
        for (int c = 0; c < CLS; c++) acc[c] += __shfl_xor_sync(0xffffffffu, acc[c], o);
    if (lane == 0) {
#pragma unroll
        for (int c = 0; c < CLS; c++) g_h2[warp * CLS + c] = acc[c];
    }
}

__global__ void alpha2_kernel(const float* __restrict__ a_s, const float* __restrict__ a_d) {
    int n = blockIdx.x * blockDim.x + threadIdx.x;
    if (n >= NN) return;
    float s = 0.f, d = 0.f;
#pragma unroll
    for (int c = 0; c < CLS; c++) {
        float v = g_h2[n * CLS + c];
        s = fmaf(v, a_s[c], s);
        d = fmaf(v, a_d[c], d);
    }
    g_as2[n] = s;
    g_ad2[n] = d;
}

__global__ __launch_bounds__(128) void agg2_kernel(const float* __restrict__ b2,
                                                   float* __restrict__ out) {
    int n = blockIdx.x * 4 + (threadIdx.x >> 5);
    int lane = threadIdx.x & 31;
    if (n >= NN) return;
    int s0 = g_off[n];
    int deg = g_off[n + 1] - s0;
    float ad = g_ad2[n];

    float lmax = -INFINITY;
    for (int i = lane; i < deg; i += 32) {
        int s = g_srcs[s0 + i];
        lmax = fmaxf(lmax, lrelu(g_as2[s] + ad));
    }
#pragma unroll
    for (int o = 16; o; o >>= 1) lmax = fmaxf(lmax, __shfl_xor_sync(0xffffffffu, lmax, o));

    float lsum = 0.f;
    for (int i = lane; i < deg; i += 32) {
        int s = g_srcs[s0 + i];
        lsum += expf(lrelu(g_as2[s] + ad) - lmax);
    }
#pragma unroll
    for (int o = 16; o; o >>= 1) lsum += __shfl_xor_sync(0xffffffffu, lsum, o);
    float inv = 1.0f / lsum;

    float acc[CLS] = {0.f, 0.f, 0.f, 0.f, 0.f, 0.f};
    for (int i = lane; i < deg; i += 32) {
        int s = g_srcs[s0 + i];
        float coef = expf(lrelu(g_as2[s] + ad) - lmax) * inv;
        const float* hp = g_h2 + s * CLS;
#pragma unroll
        for (int c = 0; c < CLS; c++) acc[c] = fmaf(coef, hp[c], acc[c]);
    }
#pragma unroll
    for (int o = 16; o; o >>= 1)
#pragma unroll
        for (int c = 0; c < CLS; c++) acc[c] += __shfl_xor_sync(0xffffffffu, acc[c], o);

    if (lane == 0) {
#pragma unroll
        for (int c = 0; c < CLS; c++) out[n * CLS + c] = acc[c] + b2[c];
    }
}

// ==================== Launch ====================
extern "C" void kernel_launch(void* const* d_in, const int* in_sizes, int n_in,
                              void* d_out, int out_size) {
    const float* x   = (const float*)d_in[0];
    const int*   ei  = (const int*)  d_in[1];
    const float* W1  = (const float*)d_in[2];
    const float* as1 = (const float*)d_in[3];
    const float* ad1 = (const float*)d_in[4];
    const float* b1  = (const float*)d_in[5];
    const float* W2  = (const float*)d_in[6];
    const float* as2 = (const float*)d_in[7];
    const float* ad2 = (const float*)d_in[8];
    const float* b2  = (const float*)d_in[9];
    float* out = (float*)d_out;

    static bool attr_set = false;
    if (!attr_set) {
        cudaFuncSetAttribute(mma1_kernel, cudaFuncAttributeMaxDynamicSharedMemorySize, SMEM_SZ);
        attr_set = true;
    }

    // CSR build
    zero_deg_kernel<<<(NN + 255) / 256, 256>>>();
    count_kernel<<<(ETOT + 255) / 256, 256>>>(ei);
    scan_kernel<<<1, 1024>>>();
    scatter_kernel<<<(ETOT + 255) / 256, 256>>>(ei);

    // W1 bf16 split (x conversion fused into mma1)
    convw1_kernel<<<dim3(D1 / 32, FIN / 32), 256>>>(W1);

    // Layer 1: fused-convert mma.sync GEMM + attention
    mma1_kernel<<<dim3(D1 / 128, (NN + 127) / 128), 256, SMEM_SZ>>>(x);
    alpha1_kernel<<<(NN + 7) / 8, 256>>>(as1, ad1);
    agg1_kernel<<<NN, 128>>>(b1);

    // Layer 2
    gemm2_kernel<<<(NN + 7) / 8, 256>>>(W2);
    alpha2_kernel<<<(NN + 255) / 256, 256>>>(as2, ad2);
    agg2_kernel<<<(NN + 3) / 4, 128>>>(b2, out);
}

// round 6
// speedup vs baseline: 2.2410x; 1.7982x over previous
#include <cuda_runtime.h>
#include <cuda_fp16.h>
#include <math.h>
#include <stdint.h>

// ---------------- Problem constants ----------------
#define NN    30000
#define EE    480000
#define ETOT  (EE + NN)
#define FIN   4096
#define D1    512
#define H1    4
#define C1    128
#define CLS   6
#define SLOPE 0.2f

// ---------------- Device scratch ----------------
__device__ float g_h1[(size_t)NN * D1];
__device__ float g_out1[(size_t)NN * D1];
__device__ float g_asrc1[NN * H1];
__device__ float g_adst1[NN * H1];
__device__ float g_h2[NN * CLS];
__device__ float g_as2[NN];
__device__ float g_ad2[NN];
__device__ int   g_deg[NN];
__device__ int   g_off[NN + 1];
__device__ int   g_cur[NN];
__device__ int   g_srcs[ETOT];

// fp16 W1 transposed: [N=512][K=4096]
__device__ __half g_w1t[(size_t)D1 * FIN];

__device__ __forceinline__ float lrelu(float v) { return v > 0.0f ? v : SLOPE * v; }

// ==================== helpers ====================
__device__ __forceinline__ uint32_t smem_u32(const void* p) {
    uint32_t a;
    asm("{ .reg .u64 t; cvta.to.shared.u64 t, %1; cvt.u32.u64 %0, t; }" : "=r"(a) : "l"(p));
    return a;
}

__device__ __forceinline__ void cpa16(uint32_t dst, const void* src) {
    asm volatile("cp.async.cg.shared.global [%0], [%1], 16;\n"
                 :: "r"(dst), "l"(src) : "memory");
}

__device__ __forceinline__ void ldm_x4(uint32_t addr, uint32_t& r0, uint32_t& r1,
                                       uint32_t& r2, uint32_t& r3) {
    asm volatile("ldmatrix.sync.aligned.m8n8.x4.shared.b16 {%0,%1,%2,%3}, [%4];"
                 : "=r"(r0), "=r"(r1), "=r"(r2), "=r"(r3) : "r"(addr));
}

__device__ __forceinline__ void mma_f16(float& d0, float& d1, float& d2, float& d3,
                                        uint32_t a0, uint32_t a1, uint32_t a2, uint32_t a3,
                                        uint32_t b0, uint32_t b1) {
    asm volatile("mma.sync.aligned.m16n8k16.row.col.f32.f16.f16.f32 "
                 "{%0,%1,%2,%3}, {%4,%5,%6,%7}, {%8,%9}, {%0,%1,%2,%3};"
                 : "+f"(d0), "+f"(d1), "+f"(d2), "+f"(d3)
                 : "r"(a0), "r"(a1), "r"(a2), "r"(a3), "r"(b0), "r"(b1));
}

__device__ __forceinline__ uint32_t pack_h2(float a, float b) {
    __half2 h = __halves2half2(__float2half_rn(a), __float2half_rn(b));
    return *(uint32_t*)&h;
}

// ==================== W1 -> fp16 transposed (32x32 tile) ====================
__global__ __launch_bounds__(256) void convw1_kernel(const float* __restrict__ W1) {
    __shared__ float tile[32][33];
    const int kb = blockIdx.y * 32;
    const int nb = blockIdx.x * 32;
    const int t = threadIdx.x;
    const int r = t >> 5, c = t & 31;
#pragma unroll
    for (int rr = r; rr < 32; rr += 8)
        tile[rr][c] = W1[(size_t)(kb + rr) * D1 + nb + c];
    __syncthreads();
#pragma unroll
    for (int rr = r; rr < 32; rr += 8) {
        float v = tile[c][rr];
        g_w1t[(size_t)(nb + rr) * FIN + kb + c] = __float2half_rn(v);
    }
}

// ==================== GEMM1: fused-convert fp16 mma.sync, 128x256 tile ====================
#define BK       32
#define CHUNKS   (FIN / BK)      // 128
#define TILE_A_B (128 * 80)      // 10240
#define TILE_B_B (256 * 80)      // 20480
#define OFF_A    0
#define OFF_B    (TILE_A_B)
#define STAGE_B  (TILE_A_B + TILE_B_B)   // 30720
#define SMEM_SZ  (2 * STAGE_B)           // 61440

__global__ __launch_bounds__(256) void mma1_kernel(const float* __restrict__ x) {
    extern __shared__ __align__(16) char dsm[];
    const uint32_t sb = smem_u32(dsm);

    const int tid = threadIdx.x;
    const int wid = tid >> 5;
    const int lane = tid & 31;
    const int warp_m = wid >> 2;    // 0..1
    const int warp_n = wid & 3;     // 0..3
    const int block_row = blockIdx.y * 128;
    const int nbase = blockIdx.x * 256;

    // A reg-staging: thread owns row r = tid>>1, 16 floats at col half*16
    const int a_r = tid >> 1;
    const int a_half = tid & 1;
    const bool a_ok = (block_row + a_r) < NN;
    const float* a_src = x + (size_t)(block_row + a_r) * FIN + a_half * 16;
    const uint32_t a_dso = (uint32_t)(a_r * 80 + a_half * 32);

    float4 xr[4];
    auto ldA = [&](int c) {
        if (a_ok) {
            const float4* p = (const float4*)(a_src + c * BK);
#pragma unroll
            for (int q = 0; q < 4; q++) xr[q] = p[q];
        } else {
            float4 z = make_float4(0.f, 0.f, 0.f, 0.f);
#pragma unroll
            for (int q = 0; q < 4; q++) xr[q] = z;
        }
    };
    auto stsA = [&](int s) {
        const uint32_t base = sb + s * STAGE_B;
        uint4 h0, h1;
        h0.x = pack_h2(xr[0].x, xr[0].y); h0.y = pack_h2(xr[0].z, xr[0].w);
        h0.z = pack_h2(xr[1].x, xr[1].y); h0.w = pack_h2(xr[1].z, xr[1].w);
        h1.x = pack_h2(xr[2].x, xr[2].y); h1.y = pack_h2(xr[2].z, xr[2].w);
        h1.z = pack_h2(xr[3].x, xr[3].y); h1.w = pack_h2(xr[3].z, xr[3].w);
        uint32_t ah = base + OFF_A + a_dso;
        asm volatile("st.shared.v4.b32 [%0], {%1,%2,%3,%4};" :: "r"(ah), "r"(h0.x), "r"(h0.y), "r"(h0.z), "r"(h0.w));
        asm volatile("st.shared.v4.b32 [%0], {%1,%2,%3,%4};" :: "r"(ah + 16), "r"(h1.x), "r"(h1.y), "r"(h1.z), "r"(h1.w));
    };

    auto cpB = [&](int c, int s) {
        const uint32_t base = sb + s * STAGE_B;
        const int kbase = c * BK;
#pragma unroll
        for (int i = tid; i < 1024; i += 256) {
            int r = i >> 2, q = i & 3;
            uint32_t dso = (uint32_t)(r * 80 + q * 16);
            size_t se = (size_t)(nbase + r) * FIN + kbase + q * 8;
            cpa16(base + OFF_B + dso, g_w1t + se);
        }
    };

    const uint32_t a_off = (uint32_t)((warp_m * 64 + (lane & 15)) * 80 + (lane >> 4) * 16);
    const uint32_t b_off = (uint32_t)((warp_n * 64 + (lane & 7) + ((lane >> 4) << 3)) * 80 +
                                      ((lane >> 3) & 1) * 16);

    float acc[4][8][4];
#pragma unroll
    for (int i = 0; i < 4; i++)
#pragma unroll
        for (int j = 0; j < 8; j++)
#pragma unroll
            for (int q = 0; q < 4; q++) acc[i][j][q] = 0.0f;

    // prologue
    ldA(0);
    stsA(0);
    cpB(0, 0);
    asm volatile("cp.async.commit_group;\n" ::: "memory");
    ldA(1);

    for (int c = 0; c < CHUNKS; c++) {
        const int s = c & 1;
        asm volatile("cp.async.wait_group 0;\n" ::: "memory");
        __syncthreads();

        if (c + 1 < CHUNKS) {
            stsA(s ^ 1);
            cpB(c + 1, s ^ 1);
            asm volatile("cp.async.commit_group;\n" ::: "memory");
        }
        if (c + 2 < CHUNKS) ldA(c + 2);

        const uint32_t stg = sb + s * STAGE_B;
        const uint32_t a_base = stg + OFF_A + a_off;
        const uint32_t b_base = stg + OFF_B + b_off;

#pragma unroll
        for (int kk = 0; kk < 2; kk++) {
            uint32_t av[4][4];
#pragma unroll
            for (int i = 0; i < 4; i++) {
                uint32_t ao = (uint32_t)(i * 16 * 80 + kk * 32);
                ldm_x4(a_base + ao, av[i][0], av[i][1], av[i][2], av[i][3]);
            }
#pragma unroll
            for (int j2 = 0; j2 < 4; j2++) {
                uint32_t b0, b1, b2, b3;
                uint32_t bo = (uint32_t)(j2 * 16 * 80 + kk * 32);
                ldm_x4(b_base + bo, b0, b1, b2, b3);
#pragma unroll
                for (int i = 0; i < 4; i++) {
                    float* d0 = acc[i][2 * j2];
                    float* d1 = acc[i][2 * j2 + 1];
                    mma_f16(d0[0], d0[1], d0[2], d0[3],
                            av[i][0], av[i][1], av[i][2], av[i][3], b0, b1);
                    mma_f16(d1[0], d1[1], d1[2], d1[3],
                            av[i][0], av[i][1], av[i][2], av[i][3], b2, b3);
                }
            }
        }
    }

    // epilogue
#pragma unroll
    for (int i = 0; i < 4; i++) {
        int row0 = block_row + warp_m * 64 + i * 16 + (lane >> 2);
#pragma unroll
        for (int j = 0; j < 8; j++) {
            int col = nbase + warp_n * 64 + j * 8 + (lane & 3) * 2;
            if (row0 < NN)
                *(float2*)(g_h1 + (size_t)row0 * D1 + col) = make_float2(acc[i][j][0], acc[i][j][1]);
            if (row0 + 8 < NN)
                *(float2*)(g_h1 + (size_t)(row0 + 8) * D1 + col) = make_float2(acc[i][j][2], acc[i][j][3]);
        }
    }
}

// ==================== CSR build ====================
__global__ void zero_deg_kernel() {
    int i = blockIdx.x * blockDim.x + threadIdx.x;
    if (i < NN) g_deg[i] = 0;
}

__global__ void count_kernel(const int* __restrict__ ei) {
    int e = blockIdx.x * blockDim.x + threadIdx.x;
    if (e >= ETOT) return;
    int dst = (e < EE) ? ei[EE + e] : (e - EE);
    atomicAdd(&g_deg[dst], 1);
}

__global__ __launch_bounds__(1024) void scan_kernel() {
    __shared__ int part[1024];
    const int t = threadIdx.x;
    const int CH = (NN + 1023) / 1024;
    const int base = t * CH;
    int s = 0;
    for (int i = 0; i < CH; i++) {
        int idx = base + i;
        if (idx < NN) s += g_deg[idx];
    }
    part[t] = s;
    __syncthreads();
    for (int o = 1; o < 1024; o <<= 1) {
        int v = (t >= o) ? part[t - o] : 0;
        __syncthreads();
        part[t] += v;
        __syncthreads();
    }
    int run = part[t] - s;
    for (int i = 0; i < CH; i++) {
        int idx = base + i;
        if (idx < NN) {
            g_off[idx] = run;
            g_cur[idx] = run;
            run += g_deg[idx];
        }
    }
    if (t == 1023) g_off[NN] = part[1023];
}

__global__ void scatter_kernel(const int* __restrict__ ei) {
    int e = blockIdx.x * blockDim.x + threadIdx.x;
    if (e >= ETOT) return;
    int src, dst;
    if (e < EE) { src = ei[e]; dst = ei[EE + e]; }
    else        { src = e - EE; dst = e - EE; }
    int pos = atomicAdd(&g_cur[dst], 1);
    g_srcs[pos] = src;
}

// ==================== Layer 1 alphas ====================
__global__ void alpha1_kernel(const float* __restrict__ a_s, const float* __restrict__ a_d) {
    int warp = blockIdx.x * 8 + (threadIdx.x >> 5);
    int lane = threadIdx.x & 31;
    if (warp >= NN) return;
    const float* row = g_h1 + (size_t)warp * D1;
#pragma unroll
    for (int h = 0; h < H1; h++) {
        float ss = 0.f, sd = 0.f;
#pragma unroll
        for (int k = 0; k < 4; k++) {
            int c = h * C1 + lane + 32 * k;
            float v = row[c];
            ss = fmaf(v, a_s[c], ss);
            sd = fmaf(v, a_d[c], sd);
        }
#pragma unroll
        for (int o = 16; o; o >>= 1) {
            ss += __shfl_xor_sync(0xffffffffu, ss, o);
            sd += __shfl_xor_sync(0xffffffffu, sd, o);
        }
        if (lane == 0) {
            g_asrc1[warp * H1 + h] = ss;
            g_adst1[warp * H1 + h] = sd;
        }
    }
}

// ==================== Layer 1 softmax + aggregate + ELU (float4 channels) ====================
__global__ __launch_bounds__(128) void agg1_kernel(const float* __restrict__ b1) {
    const int n = blockIdx.x;
    const int t = threadIdx.x;
    const int h = t >> 5;            // head owned by this thread's 4 channels
    const int s0 = g_off[n];
    const int deg = g_off[n + 1] - s0;

    __shared__ float adsts[H1];
    __shared__ float sm[H1];
    __shared__ float sinv[H1];
    __shared__ float red[128 * H1];
    __shared__ int   ssrc[128];
    __shared__ float scoef[128 * H1];

    if (t < H1) adsts[t] = g_adst1[n * H1 + t];
    __syncthreads();

    const float4* asrc4 = (const float4*)g_asrc1;

    // phase 1: per-head max
    float lm[H1] = {-INFINITY, -INFINITY, -INFINITY, -INFINITY};
    for (int i = t; i < deg; i += 128) {
        float4 as = asrc4[g_srcs[s0 + i]];
        lm[0] = fmaxf(lm[0], lrelu(as.x + adsts[0]));
        lm[1] = fmaxf(lm[1], lrelu(as.y + adsts[1]));
        lm[2] = fmaxf(lm[2], lrelu(as.z + adsts[2]));
        lm[3] = fmaxf(lm[3], lrelu(as.w + adsts[3]));
    }
#pragma unroll
    for (int hh = 0; hh < H1; hh++) red[t * H1 + hh] = lm[hh];
    __syncthreads();
    if (t < H1) {
        float m = -INFINITY;
        for (int i = 0; i < 128; i++) m = fmaxf(m, red[i * H1 + t]);
        sm[t] = m;
    }
    __syncthreads();

    // phase 2: denominators
    float ls[H1] = {0.f, 0.f, 0.f, 0.f};
    for (int i = t; i < deg; i += 128) {
        float4 as = asrc4[g_srcs[s0 + i]];
        ls[0] += expf(lrelu(as.x + adsts[0]) - sm[0]);
        ls[1] += expf(lrelu(as.y + adsts[1]) - sm[1]);
        ls[2] += expf(lrelu(as.z + adsts[2]) - sm[2]);
        ls[3] += expf(lrelu(as.w + adsts[3]) - sm[3]);
    }
#pragma unroll
    for (int hh = 0; hh < H1; hh++) red[t * H1 + hh] = ls[hh];
    __syncthreads();
    if (t < H1) {
        float s = 0.f;
        for (int i = 0; i < 128; i++) s += red[i * H1 + t];
        sinv[t] = 1.0f / s;
    }
    __syncthreads();

    // phase 3: aggregation; thread t accumulates channels [4t, 4t+4)
    float ax = 0.f, ay = 0.f, az = 0.f, aw = 0.f;
    for (int base = 0; base < deg; base += 128) {
        int cnt = min(128, deg - base);
        if (t < cnt) {
            int s = g_srcs[s0 + base + t];
            ssrc[t] = s;
            float4 as = asrc4[s];
            scoef[t * H1 + 0] = expf(lrelu(as.x + adsts[0]) - sm[0]) * sinv[0];
            scoef[t * H1 + 1] = expf(lrelu(as.y + adsts[1]) - sm[1]) * sinv[1];
            scoef[t * H1 + 2] = expf(lrelu(as.z + adsts[2]) - sm[2]) * sinv[2];
            scoef[t * H1 + 3] = expf(lrelu(as.w + adsts[3]) - sm[3]) * sinv[3];
        }
        __syncthreads();
        int i = 0;
        for (; i + 2 <= cnt; i += 2) {
            int sA = ssrc[i], sB = ssrc[i + 1];
            float4 vA = *(const float4*)(g_h1 + (size_t)sA * D1 + 4 * t);
            float4 vB = *(const float4*)(g_h1 + (size_t)sB * D1 + 4 * t);
            float cA = scoef[i * H1 + h];
            float cB = scoef[(i + 1) * H1 + h];
            ax = fmaf(cA, vA.x, ax); ay = fmaf(cA, vA.y, ay);
            az = fmaf(cA, vA.z, az); aw = fmaf(cA, vA.w, aw);
            ax = fmaf(cB, vB.x, ax); ay = fmaf(cB, vB.y, ay);
            az = fmaf(cB, vB.z, az); aw = fmaf(cB, vB.w, aw);
        }
        if (i < cnt) {
            float4 v = *(const float4*)(g_h1 + (size_t)ssrc[i] * D1 + 4 * t);
            float cf = scoef[i * H1 + h];
            ax = fmaf(cf, v.x, ax); ay = fmaf(cf, v.y, ay);
            az = fmaf(cf, v.z, az); aw = fmaf(cf, v.w, aw);
        }
        __syncthreads();
    }

    // bias + ELU, write channels [4t, 4t+4)
    float4 bb = *(const float4*)(b1 + 4 * t);
    float4 o;
    o.x = ax + bb.x; o.x = o.x > 0.f ? o.x : expm1f(o.x);
    o.y = ay + bb.y; o.y = o.y > 0.f ? o.y : expm1f(o.y);
    o.z = az + bb.z; o.z = o.z > 0.f ? o.z : expm1f(o.z);
    o.w = aw + bb.w; o.w = o.w > 0.f ? o.w : expm1f(o.w);
    *(float4*)(g_out1 + (size_t)n * D1 + 4 * t) = o;
}

// ==================== Layer 2 ====================
__global__ __launch_bounds__(256) void gemm2_kernel(const float* __restrict__ W2) {
    __shared__ float w[D1 * CLS];
    int t = threadIdx.x;
    for (int i = t; i < D1 * CLS; i += 256) w[i] = W2[i];
    __syncthreads();
    int warp = blockIdx.x * 8 + (t >> 5);
    int lane = t & 31;
    if (warp >= NN) return;
    const float* row = g_out1 + (size_t)warp * D1;
    float acc[CLS] = {0.f, 0.f, 0.f, 0.f, 0.f, 0.f};
    for (int k = lane; k < D1; k += 32) {
        float v = row[k];
        const float* wr = &w[k * CLS];
#pragma unroll
        for (int c = 0; c < CLS; c++) acc[c] = fmaf(v, wr[c], acc[c]);
    }
#pragma unroll
    for (int o = 16; o; o >>= 1)
#pragma unroll
        for (int c = 0; c < CLS; c++) acc[c] += __shfl_xor_sync(0xffffffffu, acc[c], o);
    if (lane == 0) {
#pragma unroll
        for (int c = 0; c < CLS; c++) g_h2[warp * CLS + c] = acc[c];
    }
}

__global__ void alpha2_kernel(const float* __restrict__ a_s, const float* __restrict__ a_d) {
    int n = blockIdx.x * blockDim.x + threadIdx.x;
    if (n >= NN) return;
    float s = 0.f, d = 0.f;
#pragma unroll
    for (int c = 0; c < CLS; c++) {
        float v = g_h2[n * CLS + c];
        s = fmaf(v, a_s[c], s);
        d = fmaf(v, a_d[c], d);
    }
    g_as2[n] = s;
    g_ad2[n] = d;
}

__global__ __launch_bounds__(128) void agg2_kernel(const float* __restrict__ b2,
                                                   float* __restrict__ out) {
    int n = blockIdx.x * 4 + (threadIdx.x >> 5);
    int lane = threadIdx.x & 31;
    if (n >= NN) return;
    int s0 = g_off[n];
    int deg = g_off[n + 1] - s0;
    float ad = g_ad2[n];

    float lmax = -INFINITY;
    for (int i = lane; i < deg; i += 32) {
        int s = g_srcs[s0 + i];
        lmax = fmaxf(lmax, lrelu(g_as2[s] + ad));
    }
#pragma unroll
    for (int o = 16; o; o >>= 1) lmax = fmaxf(lmax, __shfl_xor_sync(0xffffffffu, lmax, o));

    float lsum = 0.f;
    for (int i = lane; i < deg; i += 32) {
        int s = g_srcs[s0 + i];
        lsum += expf(lrelu(g_as2[s] + ad) - lmax);
    }
#pragma unroll
    for (int o = 16; o; o >>= 1) lsum += __shfl_xor_sync(0xffffffffu, lsum, o);
    float inv = 1.0f / lsum;

    float acc[CLS] = {0.f, 0.f, 0.f, 0.f, 0.f, 0.f};
    for (int i = lane; i < deg; i += 32) {
        int s = g_srcs[s0 + i];
        float coef = expf(lrelu(g_as2[s] + ad) - lmax) * inv;
        const float* hp = g_h2 + s * CLS;
#pragma unroll
        for (int c = 0; c < CLS; c++) acc[c] = fmaf(coef, hp[c], acc[c]);
    }
#pragma unroll
    for (int o = 16; o; o >>= 1)
#pragma unroll
        for (int c = 0; c < CLS; c++) acc[c] += __shfl_xor_sync(0xffffffffu, acc[c], o);

    if (lane == 0) {
#pragma unroll
        for (int c = 0; c < CLS; c++) out[n * CLS + c] = acc[c] + b2[c];
    }
}

// ==================== Launch ====================
extern "C" void kernel_launch(void* const* d_in, const int* in_sizes, int n_in,
                              void* d_out, int out_size) {
    const float* x   = (const float*)d_in[0];
    const int*   ei  = (const int*)  d_in[1];
    const float* W1  = (const float*)d_in[2];
    const float* as1 = (const float*)d_in[3];
    const float* ad1 = (const float*)d_in[4];
    const float* b1  = (const float*)d_in[5];
    const float* W2  = (const float*)d_in[6];
    const float* as2 = (const float*)d_in[7];
    const float* ad2 = (const float*)d_in[8];
    const float* b2  = (const float*)d_in[9];
    float* out = (float*)d_out;

    static bool attr_set = false;
    if (!attr_set) {
        cudaFuncSetAttribute(mma1_kernel, cudaFuncAttributeMaxDynamicSharedMemorySize, SMEM_SZ);
        attr_set = true;
    }

    // CSR build
    zero_deg_kernel<<<(NN + 255) / 256, 256>>>();
    count_kernel<<<(ETOT + 255) / 256, 256>>>(ei);
    scan_kernel<<<1, 1024>>>();
    scatter_kernel<<<(ETOT + 255) / 256, 256>>>(ei);

    // W1 -> fp16 transposed
    convw1_kernel<<<dim3(D1 / 32, FIN / 32), 256>>>(W1);

    // Layer 1: single fp16 GEMM + attention
    mma1_kernel<<<dim3(D1 / 256, (NN + 127) / 128), 256, SMEM_SZ>>>(x);
    alpha1_kernel<<<(NN + 7) / 8, 256>>>(as1, ad1);
    agg1_kernel<<<NN, 128>>>(b1);

    // Layer 2
    gemm2_kernel<<<(NN + 7) / 8, 256>>>(W2);
    alpha2_kernel<<<(NN + 255) / 256, 256>>>(as2, ad2);
    agg2_kernel<<<(NN + 3) / 4, 128>>>(b2, out);
}

// round 7
// speedup vs baseline: 2.3113x; 1.0314x over previous
#include <cuda_runtime.h>
#include <cuda_fp16.h>
#include <math.h>
#include <stdint.h>

// ---------------- Problem constants ----------------
#define NN    30000
#define EE    480000
#define ETOT  (EE + NN)
#define FIN   4096
#define D1    512
#define H1    4
#define C1    128
#define CLS   6
#define SLOPE 0.2f

// ---------------- Device scratch ----------------
__device__ __half g_h1h[(size_t)NN * D1];   // layer-1 linear output, fp16
__device__ float g_out1[(size_t)NN * D1];   // post-attention + ELU (fp32)
__device__ float g_asrc1[NN * H1];
__device__ float g_adst1[NN * H1];
__device__ float g_h2[NN * CLS];
__device__ float g_as2[NN];
__device__ float g_ad2[NN];
__device__ int   g_deg[NN];
__device__ int   g_off[NN + 1];
__device__ int   g_cur[NN];
__device__ int   g_srcs[ETOT];

// fp16 W1 transposed: [N=512][K=4096]
__device__ __half g_w1t[(size_t)D1 * FIN];

__device__ __forceinline__ float lrelu(float v) { return v > 0.0f ? v : SLOPE * v; }

// ==================== helpers ====================
__device__ __forceinline__ uint32_t smem_u32(const void* p) {
    uint32_t a;
    asm("{ .reg .u64 t; cvta.to.shared.u64 t, %1; cvt.u32.u64 %0, t; }" : "=r"(a) : "l"(p));
    return a;
}

__device__ __forceinline__ void cpa16(uint32_t dst, const void* src) {
    asm volatile("cp.async.cg.shared.global [%0], [%1], 16;\n"
                 :: "r"(dst), "l"(src) : "memory");
}

__device__ __forceinline__ void ldm_x4(uint32_t addr, uint32_t& r0, uint32_t& r1,
                                       uint32_t& r2, uint32_t& r3) {
    asm volatile("ldmatrix.sync.aligned.m8n8.x4.shared.b16 {%0,%1,%2,%3}, [%4];"
                 : "=r"(r0), "=r"(r1), "=r"(r2), "=r"(r3) : "r"(addr));
}

__device__ __forceinline__ void mma_f16(float& d0, float& d1, float& d2, float& d3,
                                        uint32_t a0, uint32_t a1, uint32_t a2, uint32_t a3,
                                        uint32_t b0, uint32_t b1) {
    asm volatile("mma.sync.aligned.m16n8k16.row.col.f32.f16.f16.f32 "
                 "{%0,%1,%2,%3}, {%4,%5,%6,%7}, {%8,%9}, {%0,%1,%2,%3};"
                 : "+f"(d0), "+f"(d1), "+f"(d2), "+f"(d3)
                 : "r"(a0), "r"(a1), "r"(a2), "r"(a3), "r"(b0), "r"(b1));
}

__device__ __forceinline__ uint32_t pack_h2(float a, float b) {
    __half2 h = __halves2half2(__float2half_rn(a), __float2half_rn(b));
    return *(uint32_t*)&h;
}

// ==================== W1 -> fp16 transposed (32x32 tile) ====================
__global__ __launch_bounds__(256) void convw1_kernel(const float* __restrict__ W1) {
    __shared__ float tile[32][33];
    const int kb = blockIdx.y * 32;
    const int nb = blockIdx.x * 32;
    const int t = threadIdx.x;
    const int r = t >> 5, c = t & 31;
#pragma unroll
    for (int rr = r; rr < 32; rr += 8)
        tile[rr][c] = W1[(size_t)(kb + rr) * D1 + nb + c];
    __syncthreads();
#pragma unroll
    for (int rr = r; rr < 32; rr += 8) {
        float v = tile[c][rr];
        g_w1t[(size_t)(nb + rr) * FIN + kb + c] = __float2half_rn(v);
    }
}

// ==================== GEMM1: fused-convert fp16 mma.sync, 128x256 tile ====================
#define BK       32
#define CHUNKS   (FIN / BK)      // 128
#define TILE_A_B (128 * 80)      // 10240
#define TILE_B_B (256 * 80)      // 20480
#define OFF_A    0
#define OFF_B    (TILE_A_B)
#define STAGE_B  (TILE_A_B + TILE_B_B)   // 30720
#define SMEM_SZ  (2 * STAGE_B)           // 61440

__global__ __launch_bounds__(256) void mma1_kernel(const float* __restrict__ x) {
    extern __shared__ __align__(16) char dsm[];
    const uint32_t sb = smem_u32(dsm);

    const int tid = threadIdx.x;
    const int wid = tid >> 5;
    const int lane = tid & 31;
    const int warp_m = wid >> 2;    // 0..1
    const int warp_n = wid & 3;     // 0..3
    const int block_row = blockIdx.y * 128;
    const int nbase = blockIdx.x * 256;

    const int a_r = tid >> 1;
    const int a_half = tid & 1;
    const bool a_ok = (block_row + a_r) < NN;
    const float* a_src = x + (size_t)(block_row + a_r) * FIN + a_half * 16;
    const uint32_t a_dso = (uint32_t)(a_r * 80 + a_half * 32);

    float4 xr[4];
    auto ldA = [&](int c) {
        if (a_ok) {
            const float4* p = (const float4*)(a_src + c * BK);
#pragma unroll
            for (int q = 0; q < 4; q++) xr[q] = p[q];
        } else {
            float4 z = make_float4(0.f, 0.f, 0.f, 0.f);
#pragma unroll
            for (int q = 0; q < 4; q++) xr[q] = z;
        }
    };
    auto stsA = [&](int s) {
        const uint32_t base = sb + s * STAGE_B;
        uint4 h0, h1;
        h0.x = pack_h2(xr[0].x, xr[0].y); h0.y = pack_h2(xr[0].z, xr[0].w);
        h0.z = pack_h2(xr[1].x, xr[1].y); h0.w = pack_h2(xr[1].z, xr[1].w);
        h1.x = pack_h2(xr[2].x, xr[2].y); h1.y = pack_h2(xr[2].z, xr[2].w);
        h1.z = pack_h2(xr[3].x, xr[3].y); h1.w = pack_h2(xr[3].z, xr[3].w);
        uint32_t ah = base + OFF_A + a_dso;
        asm volatile("st.shared.v4.b32 [%0], {%1,%2,%3,%4};" :: "r"(ah), "r"(h0.x), "r"(h0.y), "r"(h0.z), "r"(h0.w));
        asm volatile("st.shared.v4.b32 [%0], {%1,%2,%3,%4};" :: "r"(ah + 16), "r"(h1.x), "r"(h1.y), "r"(h1.z), "r"(h1.w));
    };

    auto cpB = [&](int c, int s) {
        const uint32_t base = sb + s * STAGE_B;
        const int kbase = c * BK;
#pragma unroll
        for (int i = tid; i < 1024; i += 256) {
            int r = i >> 2, q = i & 3;
            uint32_t dso = (uint32_t)(r * 80 + q * 16);
            size_t se = (size_t)(nbase + r) * FIN + kbase + q * 8;
            cpa16(base + OFF_B + dso, g_w1t + se);
        }
    };

    const uint32_t a_off = (uint32_t)((warp_m * 64 + (lane & 15)) * 80 + (lane >> 4) * 16);
    const uint32_t b_off = (uint32_t)((warp_n * 64 + (lane & 7) + ((lane >> 4) << 3)) * 80 +
                                      ((lane >> 3) & 1) * 16);

    float acc[4][8][4];
#pragma unroll
    for (int i = 0; i < 4; i++)
#pragma unroll
        for (int j = 0; j < 8; j++)
#pragma unroll
            for (int q = 0; q < 4; q++) acc[i][j][q] = 0.0f;

    ldA(0);
    stsA(0);
    cpB(0, 0);
    asm volatile("cp.async.commit_group;\n" ::: "memory");
    ldA(1);

    for (int c = 0; c < CHUNKS; c++) {
        const int s = c & 1;
        asm volatile("cp.async.wait_group 0;\n" ::: "memory");
        __syncthreads();

        if (c + 1 < CHUNKS) {
            stsA(s ^ 1);
            cpB(c + 1, s ^ 1);
            asm volatile("cp.async.commit_group;\n" ::: "memory");
        }
        if (c + 2 < CHUNKS) ldA(c + 2);

        const uint32_t stg = sb + s * STAGE_B;
        const uint32_t a_base = stg + OFF_A + a_off;
        const uint32_t b_base = stg + OFF_B + b_off;

#pragma unroll
        for (int kk = 0; kk < 2; kk++) {
            uint32_t av[4][4];
#pragma unroll
            for (int i = 0; i < 4; i++) {
                uint32_t ao = (uint32_t)(i * 16 * 80 + kk * 32);
                ldm_x4(a_base + ao, av[i][0], av[i][1], av[i][2], av[i][3]);
            }
#pragma unroll
            for (int j2 = 0; j2 < 4; j2++) {
                uint32_t b0, b1, b2, b3;
                uint32_t bo = (uint32_t)(j2 * 16 * 80 + kk * 32);
                ldm_x4(b_base + bo, b0, b1, b2, b3);
#pragma unroll
                for (int i = 0; i < 4; i++) {
                    float* d0 = acc[i][2 * j2];
                    float* d1 = acc[i][2 * j2 + 1];
                    mma_f16(d0[0], d0[1], d0[2], d0[3],
                            av[i][0], av[i][1], av[i][2], av[i][3], b0, b1);
                    mma_f16(d1[0], d1[1], d1[2], d1[3],
                            av[i][0], av[i][1], av[i][2], av[i][3], b2, b3);
                }
            }
        }
    }

    // epilogue: write fp16 h1
#pragma unroll
    for (int i = 0; i < 4; i++) {
        int row0 = block_row + warp_m * 64 + i * 16 + (lane >> 2);
#pragma unroll
        for (int j = 0; j < 8; j++) {
            int col = nbase + warp_n * 64 + j * 8 + (lane & 3) * 2;
            if (row0 < NN)
                *(uint32_t*)(g_h1h + (size_t)row0 * D1 + col) = pack_h2(acc[i][j][0], acc[i][j][1]);
            if (row0 + 8 < NN)
                *(uint32_t*)(g_h1h + (size_t)(row0 + 8) * D1 + col) = pack_h2(acc[i][j][2], acc[i][j][3]);
        }
    }
}

// ==================== CSR build ====================
__global__ void zero_deg_kernel() {
    int i = blockIdx.x * blockDim.x + threadIdx.x;
    if (i < NN) g_deg[i] = 0;
}

__global__ void count_kernel(const int* __restrict__ ei) {
    int e = blockIdx.x * blockDim.x + threadIdx.x;
    if (e >= ETOT) return;
    int dst = (e < EE) ? ei[EE + e] : (e - EE);
    atomicAdd(&g_deg[dst], 1);
}

__global__ __launch_bounds__(1024) void scan_kernel() {
    __shared__ int part[1024];
    const int t = threadIdx.x;
    const int CH = (NN + 1023) / 1024;
    const int base = t * CH;
    int s = 0;
    for (int i = 0; i < CH; i++) {
        int idx = base + i;
        if (idx < NN) s += g_deg[idx];
    }
    part[t] = s;
    __syncthreads();
    for (int o = 1; o < 1024; o <<= 1) {
        int v = (t >= o) ? part[t - o] : 0;
        __syncthreads();
        part[t] += v;
        __syncthreads();
    }
    int run = part[t] - s;
    for (int i = 0; i < CH; i++) {
        int idx = base + i;
        if (idx < NN) {
            g_off[idx] = run;
            g_cur[idx] = run;
            run += g_deg[idx];
        }
    }
    if (t == 1023) g_off[NN] = part[1023];
}

__global__ void scatter_kernel(const int* __restrict__ ei) {
    int e = blockIdx.x * blockDim.x + threadIdx.x;
    if (e >= ETOT) return;
    int src, dst;
    if (e < EE) { src = ei[e]; dst = ei[EE + e]; }
    else        { src = e - EE; dst = e - EE; }
    int pos = atomicAdd(&g_cur[dst], 1);
    g_srcs[pos] = src;
}

// ==================== Layer 1 alphas (fp16 h1) ====================
__global__ void alpha1_kernel(const float* __restrict__ a_s, const float* __restrict__ a_d) {
    int warp = blockIdx.x * 8 + (threadIdx.x >> 5);
    int lane = threadIdx.x & 31;
    if (warp >= NN) return;
    const __half2* row2 = (const __half2*)(g_h1h + (size_t)warp * D1);
#pragma unroll
    for (int h = 0; h < H1; h++) {
        float ss = 0.f, sd = 0.f;
#pragma unroll
        for (int k = 0; k < 2; k++) {
            int p = h * 64 + lane + 32 * k;        // half2 index
            float2 v = __half22float2(row2[p]);
            int c = 2 * p;
            ss = fmaf(v.x, a_s[c], ss);     ss = fmaf(v.y, a_s[c + 1], ss);
            sd = fmaf(v.x, a_d[c], sd);     sd = fmaf(v.y, a_d[c + 1], sd);
        }
#pragma unroll
        for (int o = 16; o; o >>= 1) {
            ss += __shfl_xor_sync(0xffffffffu, ss, o);
            sd += __shfl_xor_sync(0xffffffffu, sd, o);
        }
        if (lane == 0) {
            g_asrc1[warp * H1 + h] = ss;
            g_adst1[warp * H1 + h] = sd;
        }
    }
}

// ==================== Layer 1 softmax + aggregate + ELU ====================
__global__ __launch_bounds__(128) void agg1_kernel(const float* __restrict__ b1) {
    const int n = blockIdx.x;
    const int t = threadIdx.x;
    const int h = t >> 5;
    const int s0 = g_off[n];
    const int deg = g_off[n + 1] - s0;

    __shared__ float adsts[H1];
    __shared__ float sm[H1];
    __shared__ float sinv[H1];
    __shared__ float red[128 * H1];
    __shared__ int   ssrc[128];
    __shared__ float scoef[128 * H1];

    if (t < H1) adsts[t] = g_adst1[n * H1 + t];
    __syncthreads();

    const float4* asrc4 = (const float4*)g_asrc1;

    float lm[H1] = {-INFINITY, -INFINITY, -INFINITY, -INFINITY};
    for (int i = t; i < deg; i += 128) {
        float4 as = asrc4[g_srcs[s0 + i]];
        lm[0] = fmaxf(lm[0], lrelu(as.x + adsts[0]));
        lm[1] = fmaxf(lm[1], lrelu(as.y + adsts[1]));
        lm[2] = fmaxf(lm[2], lrelu(as.z + adsts[2]));
        lm[3] = fmaxf(lm[3], lrelu(as.w + adsts[3]));
    }
#pragma unroll
    for (int hh = 0; hh < H1; hh++) red[t * H1 + hh] = lm[hh];
    __syncthreads();
    if (t < H1) {
        float m = -INFINITY;
        for (int i = 0; i < 128; i++) m = fmaxf(m, red[i * H1 + t]);
        sm[t] = m;
    }
    __syncthreads();

    float ls[H1] = {0.f, 0.f, 0.f, 0.f};
    for (int i = t; i < deg; i += 128) {
        float4 as = asrc4[g_srcs[s0 + i]];
        ls[0] += expf(lrelu(as.x + adsts[0]) - sm[0]);
        ls[1] += expf(lrelu(as.y + adsts[1]) - sm[1]);
        ls[2] += expf(lrelu(as.z + adsts[2]) - sm[2]);
        ls[3] += expf(lrelu(as.w + adsts[3]) - sm[3]);
    }
#pragma unroll
    for (int hh = 0; hh < H1; hh++) red[t * H1 + hh] = ls[hh];
    __syncthreads();
    if (t < H1) {
        float s = 0.f;
        for (int i = 0; i < 128; i++) s += red[i * H1 + t];
        sinv[t] = 1.0f / s;
    }
    __syncthreads();

    // phase 3: thread t owns channels [4t, 4t+4); fp16 gather (uint2 = 4 halves)
    float ax = 0.f, ay = 0.f, az = 0.f, aw = 0.f;
    for (int base = 0; base < deg; base += 128) {
        int cnt = min(128, deg - base);
        if (t < cnt) {
            int s = g_srcs[s0 + base + t];
            ssrc[t] = s;
            float4 as = asrc4[s];
            scoef[t * H1 + 0] = expf(lrelu(as.x + adsts[0]) - sm[0]) * sinv[0];
            scoef[t * H1 + 1] = expf(lrelu(as.y + adsts[1]) - sm[1]) * sinv[1];
            scoef[t * H1 + 2] = expf(lrelu(as.z + adsts[2]) - sm[2]) * sinv[2];
            scoef[t * H1 + 3] = expf(lrelu(as.w + adsts[3]) - sm[3]) * sinv[3];
        }
        __syncthreads();
        int i = 0;
        for (; i + 2 <= cnt; i += 2) {
            int sA = ssrc[i], sB = ssrc[i + 1];
            uint2 uA = *(const uint2*)(g_h1h + (size_t)sA * D1 + 4 * t);
            uint2 uB = *(const uint2*)(g_h1h + (size_t)sB * D1 + 4 * t);
            float2 a0 = __half22float2(*(__half2*)&uA.x);
            float2 a1 = __half22float2(*(__half2*)&uA.y);
            float2 b0 = __half22float2(*(__half2*)&uB.x);
            float2 b1 = __half22float2(*(__half2*)&uB.y);
            float cA = scoef[i * H1 + h];
            float cB = scoef[(i + 1) * H1 + h];
            ax = fmaf(cA, a0.x, ax); ay = fmaf(cA, a0.y, ay);
            az = fmaf(cA, a1.x, az); aw = fmaf(cA, a1.y, aw);
            ax = fmaf(cB, b0.x, ax); ay = fmaf(cB, b0.y, ay);
            az = fmaf(cB, b1.x, az); aw = fmaf(cB, b1.y, aw);
        }
        if (i < cnt) {
            uint2 u = *(const uint2*)(g_h1h + (size_t)ssrc[i] * D1 + 4 * t);
            float2 v0 = __half22float2(*(__half2*)&u.x);
            float2 v1 = __half22float2(*(__half2*)&u.y);
            float cf = scoef[i * H1 + h];
            ax = fmaf(cf, v0.x, ax); ay = fmaf(cf, v0.y, ay);
            az = fmaf(cf, v1.x, az); aw = fmaf(cf, v1.y, aw);
        }
        __syncthreads();
    }

    float4 bb = *(const float4*)(b1 + 4 * t);
    float4 o;
    o.x = ax + bb.x; o.x = o.x > 0.f ? o.x : expm1f(o.x);
    o.y = ay + bb.y; o.y = o.y > 0.f ? o.y : expm1f(o.y);
    o.z = az + bb.z; o.z = o.z > 0.f ? o.z : expm1f(o.z);
    o.w = aw + bb.w; o.w = o.w > 0.f ? o.w : expm1f(o.w);
    *(float4*)(g_out1 + (size_t)n * D1 + 4 * t) = o;
}

// ==================== Layer 2 ====================
__global__ __launch_bounds__(256) void gemm2_kernel(const float* __restrict__ W2) {
    __shared__ float w[D1 * CLS];
    int t = threadIdx.x;
    for (int i = t; i < D1 * CLS; i += 256) w[i] = W2[i];
    __syncthreads();
    int warp = blockIdx.x * 8 + (t >> 5);
    int lane = t & 31;
    if (warp >= NN) return;
    const float* row = g_out1 + (size_t)warp * D1;
    float acc[CLS] = {0.f, 0.f, 0.f, 0.f, 0.f, 0.f};
    for (int k = lane; k < D1; k += 32) {
        float v = row[k];
        const float* wr = &w[k * CLS];
#pragma unroll
        for (int c = 0; c < CLS; c++) acc[c] = fmaf(v, wr[c], acc[c]);
    }
#pragma unroll
    for (int o = 16; o; o >>= 1)
#pragma unroll
        for (int c = 0; c < CLS; c++) acc[c] += __shfl_xor_sync(0xffffffffu, acc[c], o);
    if (lane == 0) {
#pragma unroll
        for (int c = 0; c < CLS; c++) g_h2[warp * CLS + c] = acc[c];
    }
}

__global__ void alpha2_kernel(const float* __restrict__ a_s, const float* __restrict__ a_d) {
    int n = blockIdx.x * blockDim.x + threadIdx.x;
    if (n >= NN) return;
    float s = 0.f, d = 0.f;
#pragma unroll
    for (int c = 0; c < CLS; c++) {
        float v = g_h2[n * CLS + c];
        s = fmaf(v, a_s[c], s);
        d = fmaf(v, a_d[c], d);
    }
    g_as2[n] = s;
    g_ad2[n] = d;
}

__global__ __launch_bounds__(128) void agg2_kernel(const float* __restrict__ b2,
                                                   float* __restrict__ out) {
    int n = blockIdx.x * 4 + (threadIdx.x >> 5);
    int lane = threadIdx.x & 31;
    if (n >= NN) return;
    int s0 = g_off[n];
    int deg = g_off[n + 1] - s0;
    float ad = g_ad2[n];

    float lmax = -INFINITY;
    for (int i = lane; i < deg; i += 32) {
        int s = g_srcs[s0 + i];
        lmax = fmaxf(lmax, lrelu(g_as2[s] + ad));
    }
#pragma unroll
    for (int o = 16; o; o >>= 1) lmax = fmaxf(lmax, __shfl_xor_sync(0xffffffffu, lmax, o));

    float lsum = 0.f;
    for (int i = lane; i < deg; i += 32) {
        int s = g_srcs[s0 + i];
        lsum += expf(lrelu(g_as2[s] + ad) - lmax);
    }
#pragma unroll
    for (int o = 16; o; o >>= 1) lsum += __shfl_xor_sync(0xffffffffu, lsum, o);
    float inv = 1.0f / lsum;

    float acc[CLS] = {0.f, 0.f, 0.f, 0.f, 0.f, 0.f};
    for (int i = lane; i < deg; i += 32) {
        int s = g_srcs[s0 + i];
        float coef = expf(lrelu(g_as2[s] + ad) - lmax) * inv;
        const float* hp = g_h2 + s * CLS;
#pragma unroll
        for (int c = 0; c < CLS; c++) acc[c] = fmaf(coef, hp[c], acc[c]);
    }
#pragma unroll
    for (int o = 16; o; o >>= 1)
#pragma unroll
        for (int c = 0; c < CLS; c++) acc[c] += __shfl_xor_sync(0xffffffffu, acc[c], o);

    if (lane == 0) {
#pragma unroll
        for (int c = 0; c < CLS; c++) out[n * CLS + c] = acc[c] + b2[c];
    }
}

// ==================== Launch ====================
extern "C" void kernel_launch(void* const* d_in, const int* in_sizes, int n_in,
                              void* d_out, int out_size) {
    const float* x   = (const float*)d_in[0];
    const int*   ei  = (const int*)  d_in[1];
    const float* W1  = (const float*)d_in[2];
    const float* as1 = (const float*)d_in[3];
    const float* ad1 = (const float*)d_in[4];
    const float* b1  = (const float*)d_in[5];
    const float* W2  = (const float*)d_in[6];
    const float* as2 = (const float*)d_in[7];
    const float* ad2 = (const float*)d_in[8];
    const float* b2  = (const float*)d_in[9];
    float* out = (float*)d_out;

    static bool attr_set = false;
    if (!attr_set) {
        cudaFuncSetAttribute(mma1_kernel, cudaFuncAttributeMaxDynamicSharedMemorySize, SMEM_SZ);
        attr_set = true;
    }

    // CSR build
    zero_deg_kernel<<<(NN + 255) / 256, 256>>>();
    count_kernel<<<(ETOT + 255) / 256, 256>>>(ei);
    scan_kernel<<<1, 1024>>>();
    scatter_kernel<<<(ETOT + 255) / 256, 256>>>(ei);

    // W1 -> fp16 transposed
    convw1_kernel<<<dim3(D1 / 32, FIN / 32), 256>>>(W1);

    // Layer 1
    mma1_kernel<<<dim3(D1 / 256, (NN + 127) / 128), 256, SMEM_SZ>>>(x);
    alpha1_kernel<<<(NN + 7) / 8, 256>>>(as1, ad1);
    agg1_kernel<<<NN, 128>>>(b1);

    // Layer 2
    gemm2_kernel<<<(NN + 7) / 8, 256>>>(W2);
    alpha2_kernel<<<(NN + 255) / 256, 256>>>(as2, ad2);
    agg2_kernel<<<(NN + 3) / 4, 128>>>(b2, out);
}